// round 2
// baseline (speedup 1.0000x reference)
#include <cuda_runtime.h>
#include <math.h>

// Problem constants
#define BB 2
#define SS 1024
#define DD 1024
#define HH 16
#define DKK 64
#define FF 4096
#define VV 32000
#define LLAYERS 8
#define MM (BB*SS)          // 2048 token rows

// ---------------------------------------------------------------------------
// Scratch (allocation-free: __device__ globals)
// ---------------------------------------------------------------------------
__device__ float g_x[MM*DD];        // residual stream
__device__ float g_h[MM*DD];        // layernorm output
__device__ float g_q[MM*DD];
__device__ float g_k[MM*DD];
__device__ float g_v[MM*DD];
__device__ float g_o[MM*DD];        // attention output (pre-proj), [B,S,H,DK]
__device__ float g_ffn[MM*FF];      // FFN hidden
__device__ float g_sc[(long)BB*HH*SS*SS]; // attention scores/probs [B,H,S,S]

// ---------------------------------------------------------------------------
// Embedding: x[b,s,:] = tok_emb[ids[b,s],:] + pos_emb[s,:]
// ---------------------------------------------------------------------------
__global__ void embed_kernel(const int* __restrict__ ids,
                             const float* __restrict__ tok,
                             const float* __restrict__ pos) {
    int idx = blockIdx.x * blockDim.x + threadIdx.x;   // over MM*DD/4
    if (idx >= MM * (DD/4)) return;
    int m  = idx / (DD/4);
    int d4 = idx % (DD/4);
    int id = ids[m];
    int s  = m % SS;
    const float4* t4 = (const float4*)tok;
    const float4* p4 = (const float4*)pos;
    float4 a = t4[(long)id * (DD/4) + d4];
    float4 b = p4[(long)s  * (DD/4) + d4];
    a.x += b.x; a.y += b.y; a.z += b.z; a.w += b.w;
    ((float4*)g_x)[idx] = a;
}

// ---------------------------------------------------------------------------
// Block reduction helpers (256 threads)
// ---------------------------------------------------------------------------
__device__ __forceinline__ float block_reduce_sum(float v) {
    __shared__ float sh[8];
    __shared__ float res;
    __syncthreads();
    #pragma unroll
    for (int o = 16; o > 0; o >>= 1) v += __shfl_xor_sync(0xffffffffu, v, o);
    int w = threadIdx.x >> 5, lane = threadIdx.x & 31;
    if (lane == 0) sh[w] = v;
    __syncthreads();
    if (w == 0) {
        v = (lane < 8) ? sh[lane] : 0.0f;
        #pragma unroll
        for (int o = 4; o > 0; o >>= 1) v += __shfl_xor_sync(0xffffffffu, v, o);
        if (lane == 0) res = v;
    }
    __syncthreads();
    return res;
}

__device__ __forceinline__ float block_reduce_max(float v) {
    __shared__ float sh[8];
    __shared__ float res;
    __syncthreads();
    #pragma unroll
    for (int o = 16; o > 0; o >>= 1) v = fmaxf(v, __shfl_xor_sync(0xffffffffu, v, o));
    int w = threadIdx.x >> 5, lane = threadIdx.x & 31;
    if (lane == 0) sh[w] = v;
    __syncthreads();
    if (w == 0) {
        v = (lane < 8) ? sh[lane] : -INFINITY;
        #pragma unroll
        for (int o = 4; o > 0; o >>= 1) v = fmaxf(v, __shfl_xor_sync(0xffffffffu, v, o));
        if (lane == 0) res = v;
    }
    __syncthreads();
    return res;
}

// ---------------------------------------------------------------------------
// LayerNorm: one block (256 threads) per row of D=1024; each thread one float4
// ---------------------------------------------------------------------------
__global__ void ln_kernel(const float* __restrict__ x, float* __restrict__ y,
                          const float* __restrict__ g, const float* __restrict__ b) {
    int row = blockIdx.x;
    int t = threadIdx.x;
    const float4* xr = (const float4*)(x + (long)row * DD);
    float4 v = xr[t];
    float s = v.x + v.y + v.z + v.w;
    float mean = block_reduce_sum(s) * (1.0f / DD);
    float dx = v.x - mean, dy = v.y - mean, dz = v.z - mean, dw = v.w - mean;
    float sq = dx*dx + dy*dy + dz*dz + dw*dw;
    float var = block_reduce_sum(sq) * (1.0f / DD);
    float rs = rsqrtf(var + 1e-5f);
    const float4 gg = ((const float4*)g)[t];
    const float4 bb2 = ((const float4*)b)[t];
    float4 o;
    o.x = dx * rs * gg.x + bb2.x;
    o.y = dy * rs * gg.y + bb2.y;
    o.z = dz * rs * gg.z + bb2.z;
    o.w = dw * rs * gg.w + bb2.w;
    ((float4*)(y + (long)row * DD))[t] = o;
}

// ---------------------------------------------------------------------------
// Causal softmax over scores rows. grid = B*H*S blocks, 256 threads.
// Writes 0 for k > q (so attn @ V over full K reads clean zeros).
// ---------------------------------------------------------------------------
__global__ void softmax_kernel(float* __restrict__ sc) {
    long row = blockIdx.x;              // (b*H + h)*S + q
    int q = (int)(row % SS);
    float* p = sc + row * SS;
    int n = q + 1;
    int t = threadIdx.x;

    float mx = -INFINITY;
    for (int j = t; j < n; j += 256) mx = fmaxf(mx, p[j]);
    mx = block_reduce_max(mx);

    float sum = 0.0f;
    for (int j = t; j < n; j += 256) {
        float e = __expf(p[j] - mx);
        p[j] = e;
        sum += e;
    }
    sum = block_reduce_sum(sum);
    float inv = 1.0f / sum;
    for (int j = t; j < SS; j += 256) {
        p[j] = (j < n) ? p[j] * inv : 0.0f;
    }
}

// ---------------------------------------------------------------------------
// Generic batched SGEMM:  C = alpha * (A @ W[^T]) [+ bias] [ReLU] [+ residual]
// A: M x K row-major (lda). W: K x N row-major (ldw), or N x K if transB.
// Tiles: 128x128x8, 256 threads, 8x8 per thread.
// Batch z: offsets = (z/sub)*outer + (z%sub)*inner per operand.
// causal: skip output tiles entirely above the diagonal.
// Requires: M % 128 == 0, K % 8 == 0, lda/ldw % 4 == 0, N % 8 == 0.
// ---------------------------------------------------------------------------
__global__ __launch_bounds__(256)
void gemm_kernel(const float* __restrict__ A, const float* __restrict__ W,
                 float* __restrict__ C,
                 const float* __restrict__ bias, const float* __restrict__ residual,
                 int M, int N, int K, int lda, int ldw, int ldc,
                 float alpha, int relu, int transB, int causal,
                 long sAo, long sAi, long sWo, long sWi, long sCo, long sCi,
                 int sub) {
    if (causal && blockIdx.x > blockIdx.y) return;   // all k-cols > all q-rows

    int z = blockIdx.z;
    int zo = z / sub, zi = z % sub;
    A += zo * sAo + zi * sAi;
    W += zo * sWo + zi * sWi;
    C += zo * sCo + zi * sCi;
    if (residual) residual += zo * sCo + zi * sCi;

    __shared__ float As[8][132];   // padded to kill store bank conflicts
    __shared__ float Bs[8][128];

    int t  = threadIdx.x;
    int tx = t & 15;               // 0..15 -> output col group
    int ty = t >> 4;               // 0..15 -> output row group
    int m0 = blockIdx.y * 128;
    int n0 = blockIdx.x * 128;

    // A-tile load mapping: thread -> (row m = t>>1, 4 k's = (t&1)*4)
    int a_m  = t >> 1;
    int a_k4 = (t & 1) * 4;
    // B-tile load mapping (no trans): kk = t>>5, 4 n's = (t&31)*4
    int b_kk = t >> 5;
    int b_n4 = (t & 31) * 4;
    // B-tile load mapping (trans): n = t&127, 4 k's = (t>>7)*4
    int bt_n  = t & 127;
    int bt_k4 = (t >> 7) * 4;

    float acc[8][8];
    #pragma unroll
    for (int i = 0; i < 8; i++)
        #pragma unroll
        for (int j = 0; j < 8; j++) acc[i][j] = 0.0f;

    for (int k0 = 0; k0 < K; k0 += 8) {
        // load A tile (transposed into As[k][m])
        {
            float4 av = *(const float4*)(A + (long)(m0 + a_m) * lda + k0 + a_k4);
            As[a_k4 + 0][a_m] = av.x;
            As[a_k4 + 1][a_m] = av.y;
            As[a_k4 + 2][a_m] = av.z;
            As[a_k4 + 3][a_m] = av.w;
        }
        // load B tile
        if (!transB) {
            float4 bv;
            if (n0 + b_n4 < N)
                bv = *(const float4*)(W + (long)(k0 + b_kk) * ldw + n0 + b_n4);
            else
                bv = make_float4(0.f, 0.f, 0.f, 0.f);
            *(float4*)&Bs[b_kk][b_n4] = bv;
        } else {
            float4 bv;
            if (n0 + bt_n < N)
                bv = *(const float4*)(W + (long)(n0 + bt_n) * ldw + k0 + bt_k4);
            else
                bv = make_float4(0.f, 0.f, 0.f, 0.f);
            Bs[bt_k4 + 0][bt_n] = bv.x;
            Bs[bt_k4 + 1][bt_n] = bv.y;
            Bs[bt_k4 + 2][bt_n] = bv.z;
            Bs[bt_k4 + 3][bt_n] = bv.w;
        }
        __syncthreads();

        #pragma unroll
        for (int kk = 0; kk < 8; kk++) {
            float4 a0 = *(const float4*)&As[kk][ty * 8];
            float4 a1 = *(const float4*)&As[kk][ty * 8 + 4];
            float4 b0 = *(const float4*)&Bs[kk][tx * 8];
            float4 b1 = *(const float4*)&Bs[kk][tx * 8 + 4];
            float ar[8] = {a0.x, a0.y, a0.z, a0.w, a1.x, a1.y, a1.z, a1.w};
            float br[8] = {b0.x, b0.y, b0.z, b0.w, b1.x, b1.y, b1.z, b1.w};
            #pragma unroll
            for (int i = 0; i < 8; i++)
                #pragma unroll
                for (int j = 0; j < 8; j++)
                    acc[i][j] = fmaf(ar[i], br[j], acc[i][j]);
        }
        __syncthreads();
    }

    // Epilogue
    #pragma unroll
    for (int i = 0; i < 8; i++) {
        int m = m0 + ty * 8 + i;
        float* crow = C + (long)m * ldc;
        const float* rrow = residual ? residual + (long)m * ldc : nullptr;
        #pragma unroll
        for (int j = 0; j < 8; j++) {
            int n = n0 + tx * 8 + j;
            if (n < N) {
                float v = alpha * acc[i][j];
                if (bias) v += bias[n];
                if (relu) v = fmaxf(v, 0.0f);
                if (rrow) v += rrow[n];
                crow[n] = v;
            }
        }
    }
}

// ---------------------------------------------------------------------------
// Host-side helper
// ---------------------------------------------------------------------------
static void launch_gemm(const float* A, const float* W, float* C,
                        const float* bias, const float* residual,
                        int M, int N, int K, int lda, int ldw, int ldc,
                        float alpha, int relu, int transB, int causal,
                        int batch, int sub,
                        long sAo, long sAi, long sWo, long sWi, long sCo, long sCi) {
    dim3 grid((N + 127) / 128, (M + 127) / 128, batch);
    gemm_kernel<<<grid, 256>>>(A, W, C, bias, residual, M, N, K, lda, ldw, ldc,
                               alpha, relu, transB, causal,
                               sAo, sAi, sWo, sWi, sCo, sCi, sub);
}

extern "C" void kernel_launch(void* const* d_in, const int* in_sizes, int n_in,
                              void* d_out, int out_size) {
    const int*   ids   = (const int*)  d_in[0];
    const float* tok   = (const float*)d_in[1];
    const float* pos   = (const float*)d_in[2];
    const float* Wq    = (const float*)d_in[3];
    const float* bq    = (const float*)d_in[4];
    const float* Wk    = (const float*)d_in[5];
    const float* bk    = (const float*)d_in[6];
    const float* Wv    = (const float*)d_in[7];
    const float* bv    = (const float*)d_in[8];
    const float* Wo    = (const float*)d_in[9];
    const float* bo    = (const float*)d_in[10];
    const float* W1    = (const float*)d_in[11];
    const float* b1    = (const float*)d_in[12];
    const float* W2    = (const float*)d_in[13];
    const float* b2    = (const float*)d_in[14];
    const float* ln1g  = (const float*)d_in[15];
    const float* ln1b  = (const float*)d_in[16];
    const float* ln2g  = (const float*)d_in[17];
    const float* ln2b  = (const float*)d_in[18];
    const float* lnfg  = (const float*)d_in[19];
    const float* lnfb  = (const float*)d_in[20];
    const float* Wout  = (const float*)d_in[21];
    const float* bout  = (const float*)d_in[22];
    float* out = (float*)d_out;

    float *px, *ph, *pq, *pk, *pv, *po, *pffn, *psc;
    cudaGetSymbolAddress((void**)&px,   g_x);
    cudaGetSymbolAddress((void**)&ph,   g_h);
    cudaGetSymbolAddress((void**)&pq,   g_q);
    cudaGetSymbolAddress((void**)&pk,   g_k);
    cudaGetSymbolAddress((void**)&pv,   g_v);
    cudaGetSymbolAddress((void**)&po,   g_o);
    cudaGetSymbolAddress((void**)&pffn, g_ffn);
    cudaGetSymbolAddress((void**)&psc,  g_sc);

    const float scale = 1.0f / 8.0f;  // 1/sqrt(64)

    // Embedding
    {
        int total = MM * (DD / 4);
        embed_kernel<<<(total + 255) / 256, 256>>>(ids, tok, pos);
    }

    for (int l = 0; l < LLAYERS; l++) {
        const float* Wq_l = Wq + (long)l * DD * DD;
        const float* Wk_l = Wk + (long)l * DD * DD;
        const float* Wv_l = Wv + (long)l * DD * DD;
        const float* Wo_l = Wo + (long)l * DD * DD;
        const float* W1_l = W1 + (long)l * DD * FF;
        const float* W2_l = W2 + (long)l * FF * DD;
        const float* bq_l = bq + (long)l * DD;
        const float* bk_l = bk + (long)l * DD;
        const float* bv_l = bv + (long)l * DD;
        const float* bo_l = bo + (long)l * DD;
        const float* b1_l = b1 + (long)l * FF;
        const float* b2_l = b2 + (long)l * DD;

        // LN1
        ln_kernel<<<MM, 256>>>(px, ph, ln1g + (long)l * DD, ln1b + (long)l * DD);

        // Q, K, V projections
        launch_gemm(ph, Wq_l, pq, bq_l, nullptr, MM, DD, DD, DD, DD, DD,
                    1.0f, 0, 0, 0, 1, 1, 0, 0, 0, 0, 0, 0);
        launch_gemm(ph, Wk_l, pk, bk_l, nullptr, MM, DD, DD, DD, DD, DD,
                    1.0f, 0, 0, 0, 1, 1, 0, 0, 0, 0, 0, 0);
        launch_gemm(ph, Wv_l, pv, bv_l, nullptr, MM, DD, DD, DD, DD, DD,
                    1.0f, 0, 0, 0, 1, 1, 0, 0, 0, 0, 0, 0);

        // scores[b,h] = scale * q[b,:,h,:] @ k[b,:,h,:]^T   (lower tiles only)
        launch_gemm(pq, pk, psc, nullptr, nullptr,
                    SS, SS, DKK, DD, DD, SS,
                    scale, 0, 1, 1,
                    BB * HH, HH,
                    (long)SS * DD, DKK,        // A (q): b, h
                    (long)SS * DD, DKK,        // W (k): b, h
                    (long)HH * SS * SS, (long)SS * SS);  // C (scores)

        // causal softmax
        softmax_kernel<<<BB * HH * SS, 256>>>(psc);

        // o[b,:,h,:] = attn[b,h] @ v[b,:,h,:]
        launch_gemm(psc, pv, po, nullptr, nullptr,
                    SS, DKK, SS, SS, DD, DD,
                    1.0f, 0, 0, 0,
                    BB * HH, HH,
                    (long)HH * SS * SS, (long)SS * SS,  // A (attn)
                    (long)SS * DD, DKK,                 // W (v)
                    (long)SS * DD, DKK);                // C (o)

        // output projection + residual (in-place into x)
        launch_gemm(po, Wo_l, px, bo_l, px, MM, DD, DD, DD, DD, DD,
                    1.0f, 0, 0, 0, 1, 1, 0, 0, 0, 0, 0, 0);

        // LN2
        ln_kernel<<<MM, 256>>>(px, ph, ln2g + (long)l * DD, ln2b + (long)l * DD);

        // FFN1 with ReLU
        launch_gemm(ph, W1_l, pffn, b1_l, nullptr, MM, FF, DD, DD, FF, FF,
                    1.0f, 1, 0, 0, 1, 1, 0, 0, 0, 0, 0, 0);

        // FFN2 + residual (in-place into x)
        launch_gemm(pffn, W2_l, px, b2_l, px, MM, DD, FF, FF, DD, DD,
                    1.0f, 0, 0, 0, 1, 1, 0, 0, 0, 0, 0, 0);
    }

    // Final LN + logits
    ln_kernel<<<MM, 256>>>(px, ph, lnfg, lnfb);
    launch_gemm(ph, Wout, out, bout, nullptr, MM, VV, DD, DD, VV, VV,
                1.0f, 0, 0, 0, 1, 1, 0, 0, 0, 0, 0, 0);
}

// round 4
// speedup vs baseline: 2.4586x; 2.4586x over previous
#include <cuda_runtime.h>
#include <cuda_bf16.h>
#include <math.h>
#include <stdint.h>

// Problem constants
#define BB 2
#define SS 1024
#define DD 1024
#define HH 16
#define DKK 64
#define FF 4096
#define VV 32000
#define LLAYERS 8
#define MM (BB*SS)          // 2048 token rows

// ---------------------------------------------------------------------------
// Scratch (allocation-free: __device__ globals)
// ---------------------------------------------------------------------------
__device__ float g_x[MM*DD];          // residual stream
__device__ float g_h[MM*DD];          // layernorm output
__device__ float g_qkv[MM*3*DD];      // fused QKV output [M,3072]
__device__ float g_o[MM*DD];          // attention output (pre-proj)
__device__ float g_ffn[MM*FF];        // FFN hidden
__device__ float g_sc[(long)BB*HH*SS*SS]; // attention scores/probs [B,H,S,S]
__device__ float g_bqkv[LLAYERS*3*DD];    // concat qkv bias

// Activation split buffers (bf16 hi/lo) — sized for largest (FFN hidden)
__device__ __nv_bfloat16 g_ah[MM*FF];
__device__ __nv_bfloat16 g_al[MM*FF];

// Weight transposed+split buffers [N,K] bf16
__device__ __nv_bfloat16 g_wqkv_h[(long)LLAYERS*3*DD*DD];
__device__ __nv_bfloat16 g_wqkv_l[(long)LLAYERS*3*DD*DD];
__device__ __nv_bfloat16 g_wo_h[(long)LLAYERS*DD*DD];
__device__ __nv_bfloat16 g_wo_l[(long)LLAYERS*DD*DD];
__device__ __nv_bfloat16 g_w1_h[(long)LLAYERS*DD*FF];
__device__ __nv_bfloat16 g_w1_l[(long)LLAYERS*DD*FF];
__device__ __nv_bfloat16 g_w2_h[(long)LLAYERS*FF*DD];
__device__ __nv_bfloat16 g_w2_l[(long)LLAYERS*FF*DD];
__device__ __nv_bfloat16 g_wout_h[(long)DD*VV];
__device__ __nv_bfloat16 g_wout_l[(long)DD*VV];

// ---------------------------------------------------------------------------
// Small PTX helpers (all valid on plain sm_103 target)
// ---------------------------------------------------------------------------
__device__ __forceinline__ uint32_t s2u(const void* p) {
    return (uint32_t)__cvta_generic_to_shared(p);
}

__device__ __forceinline__ void cp16(uint32_t saddr, const void* g) {
    asm volatile("cp.async.cg.shared.global [%0], [%1], 16;" :: "r"(saddr), "l"(g));
}

__device__ __forceinline__ void ldsm4(uint32_t* r, uint32_t addr) {
    asm volatile("ldmatrix.sync.aligned.m8n8.x4.shared.b16 {%0,%1,%2,%3}, [%4];"
                 : "=r"(r[0]), "=r"(r[1]), "=r"(r[2]), "=r"(r[3]) : "r"(addr));
}

__device__ __forceinline__ void mma16816(float* d, const uint32_t* a,
                                         uint32_t b0, uint32_t b1) {
    asm volatile(
        "mma.sync.aligned.m16n8k16.row.col.f32.bf16.bf16.f32 "
        "{%0,%1,%2,%3}, {%4,%5,%6,%7}, {%8,%9}, {%0,%1,%2,%3};"
        : "+f"(d[0]), "+f"(d[1]), "+f"(d[2]), "+f"(d[3])
        : "r"(a[0]), "r"(a[1]), "r"(a[2]), "r"(a[3]), "r"(b0), "r"(b1));
}

// ---------------------------------------------------------------------------
// Embedding
// ---------------------------------------------------------------------------
__global__ void embed_kernel(const int* __restrict__ ids,
                             const float* __restrict__ tok,
                             const float* __restrict__ pos) {
    int idx = blockIdx.x * blockDim.x + threadIdx.x;
    if (idx >= MM * (DD/4)) return;
    int m  = idx / (DD/4);
    int d4 = idx % (DD/4);
    int id = ids[m];
    int s  = m % SS;
    const float4* t4 = (const float4*)tok;
    const float4* p4 = (const float4*)pos;
    float4 a = t4[(long)id * (DD/4) + d4];
    float4 b = p4[(long)s  * (DD/4) + d4];
    a.x += b.x; a.y += b.y; a.z += b.z; a.w += b.w;
    ((float4*)g_x)[idx] = a;
}

// ---------------------------------------------------------------------------
// Block reductions (256 threads)
// ---------------------------------------------------------------------------
__device__ __forceinline__ float block_reduce_sum(float v) {
    __shared__ float sh[8];
    __shared__ float res;
    __syncthreads();
    #pragma unroll
    for (int o = 16; o > 0; o >>= 1) v += __shfl_xor_sync(0xffffffffu, v, o);
    int w = threadIdx.x >> 5, lane = threadIdx.x & 31;
    if (lane == 0) sh[w] = v;
    __syncthreads();
    if (w == 0) {
        v = (lane < 8) ? sh[lane] : 0.0f;
        #pragma unroll
        for (int o = 4; o > 0; o >>= 1) v += __shfl_xor_sync(0xffffffffu, v, o);
        if (lane == 0) res = v;
    }
    __syncthreads();
    return res;
}

__device__ __forceinline__ float block_reduce_max(float v) {
    __shared__ float sh[8];
    __shared__ float res;
    __syncthreads();
    #pragma unroll
    for (int o = 16; o > 0; o >>= 1) v = fmaxf(v, __shfl_xor_sync(0xffffffffu, v, o));
    int w = threadIdx.x >> 5, lane = threadIdx.x & 31;
    if (lane == 0) sh[w] = v;
    __syncthreads();
    if (w == 0) {
        v = (lane < 8) ? sh[lane] : -INFINITY;
        #pragma unroll
        for (int o = 4; o > 0; o >>= 1) v = fmaxf(v, __shfl_xor_sync(0xffffffffu, v, o));
        if (lane == 0) res = v;
    }
    __syncthreads();
    return res;
}

// ---------------------------------------------------------------------------
// LayerNorm
// ---------------------------------------------------------------------------
__global__ void ln_kernel(const float* __restrict__ x, float* __restrict__ y,
                          const float* __restrict__ g, const float* __restrict__ b) {
    int row = blockIdx.x;
    int t = threadIdx.x;
    const float4* xr = (const float4*)(x + (long)row * DD);
    float4 v = xr[t];
    float s = v.x + v.y + v.z + v.w;
    float mean = block_reduce_sum(s) * (1.0f / DD);
    float dx = v.x - mean, dy = v.y - mean, dz = v.z - mean, dw = v.w - mean;
    float sq = dx*dx + dy*dy + dz*dz + dw*dw;
    float var = block_reduce_sum(sq) * (1.0f / DD);
    float rs = rsqrtf(var + 1e-5f);
    const float4 gg = ((const float4*)g)[t];
    const float4 bb2 = ((const float4*)b)[t];
    float4 o;
    o.x = dx * rs * gg.x + bb2.x;
    o.y = dy * rs * gg.y + bb2.y;
    o.z = dz * rs * gg.z + bb2.z;
    o.w = dw * rs * gg.w + bb2.w;
    ((float4*)(y + (long)row * DD))[t] = o;
}

// ---------------------------------------------------------------------------
// Causal softmax
// ---------------------------------------------------------------------------
__global__ void softmax_kernel(float* __restrict__ sc) {
    long row = blockIdx.x;
    int q = (int)(row % SS);
    float* p = sc + row * SS;
    int n = q + 1;
    int t = threadIdx.x;

    float mx = -INFINITY;
    for (int j = t; j < n; j += 256) mx = fmaxf(mx, p[j]);
    mx = block_reduce_max(mx);

    float sum = 0.0f;
    for (int j = t; j < n; j += 256) {
        float e = __expf(p[j] - mx);
        p[j] = e;
        sum += e;
    }
    sum = block_reduce_sum(sum);
    float inv = 1.0f / sum;
    for (int j = t; j < SS; j += 256) {
        p[j] = (j < n) ? p[j] * inv : 0.0f;
    }
}

// ---------------------------------------------------------------------------
// fp32 SGEMM (attention score / attn@V only)
// ---------------------------------------------------------------------------
__global__ __launch_bounds__(256)
void gemm_kernel(const float* __restrict__ A, const float* __restrict__ W,
                 float* __restrict__ C,
                 int M, int N, int K, int lda, int ldw, int ldc,
                 float alpha, int transB, int causal,
                 long sAo, long sAi, long sWo, long sWi, long sCo, long sCi,
                 int sub) {
    if (causal && blockIdx.x > blockIdx.y) return;

    int z = blockIdx.z;
    int zo = z / sub, zi = z % sub;
    A += zo * sAo + zi * sAi;
    W += zo * sWo + zi * sWi;
    C += zo * sCo + zi * sCi;

    __shared__ float As[8][132];
    __shared__ float Bs[8][128];

    int t  = threadIdx.x;
    int tx = t & 15;
    int ty = t >> 4;
    int m0 = blockIdx.y * 128;
    int n0 = blockIdx.x * 128;

    int a_m  = t >> 1;
    int a_k4 = (t & 1) * 4;
    int b_kk = t >> 5;
    int b_n4 = (t & 31) * 4;
    int bt_n  = t & 127;
    int bt_k4 = (t >> 7) * 4;

    float acc[8][8];
    #pragma unroll
    for (int i = 0; i < 8; i++)
        #pragma unroll
        for (int j = 0; j < 8; j++) acc[i][j] = 0.0f;

    for (int k0 = 0; k0 < K; k0 += 8) {
        {
            float4 av = *(const float4*)(A + (long)(m0 + a_m) * lda + k0 + a_k4);
            As[a_k4 + 0][a_m] = av.x;
            As[a_k4 + 1][a_m] = av.y;
            As[a_k4 + 2][a_m] = av.z;
            As[a_k4 + 3][a_m] = av.w;
        }
        if (!transB) {
            float4 bv;
            if (n0 + b_n4 < N)
                bv = *(const float4*)(W + (long)(k0 + b_kk) * ldw + n0 + b_n4);
            else
                bv = make_float4(0.f, 0.f, 0.f, 0.f);
            *(float4*)&Bs[b_kk][b_n4] = bv;
        } else {
            float4 bv;
            if (n0 + bt_n < N)
                bv = *(const float4*)(W + (long)(n0 + bt_n) * ldw + k0 + bt_k4);
            else
                bv = make_float4(0.f, 0.f, 0.f, 0.f);
            Bs[bt_k4 + 0][bt_n] = bv.x;
            Bs[bt_k4 + 1][bt_n] = bv.y;
            Bs[bt_k4 + 2][bt_n] = bv.z;
            Bs[bt_k4 + 3][bt_n] = bv.w;
        }
        __syncthreads();

        #pragma unroll
        for (int kk = 0; kk < 8; kk++) {
            float4 a0 = *(const float4*)&As[kk][ty * 8];
            float4 a1 = *(const float4*)&As[kk][ty * 8 + 4];
            float4 b0 = *(const float4*)&Bs[kk][tx * 8];
            float4 b1 = *(const float4*)&Bs[kk][tx * 8 + 4];
            float ar[8] = {a0.x, a0.y, a0.z, a0.w, a1.x, a1.y, a1.z, a1.w};
            float br[8] = {b0.x, b0.y, b0.z, b0.w, b1.x, b1.y, b1.z, b1.w};
            #pragma unroll
            for (int i = 0; i < 8; i++)
                #pragma unroll
                for (int j = 0; j < 8; j++)
                    acc[i][j] = fmaf(ar[i], br[j], acc[i][j]);
        }
        __syncthreads();
    }

    #pragma unroll
    for (int i = 0; i < 8; i++) {
        int m = m0 + ty * 8 + i;
        float* crow = C + (long)m * ldc;
        #pragma unroll
        for (int j = 0; j < 8; j++) {
            int n = n0 + tx * 8 + j;
            if (n < N) crow[n] = alpha * acc[i][j];
        }
    }
}

// ---------------------------------------------------------------------------
// Weight transpose + bf16 hi/lo split:  W [K,N] fp32 -> out [N,K] bf16 x2
// ---------------------------------------------------------------------------
__global__ void wtrans_kernel(const float* __restrict__ W,
                              __nv_bfloat16* __restrict__ hi,
                              __nv_bfloat16* __restrict__ lo,
                              int K, int N, long lsW, long lsO, int rowOff) {
    __shared__ float t[32][33];
    int l = blockIdx.z;
    const float* Wl = W + (long)l * lsW;
    int n0 = blockIdx.x * 32, k0 = blockIdx.y * 32;
    int tx = threadIdx.x, ty = threadIdx.y;
    #pragma unroll
    for (int r = ty; r < 32; r += 8)
        t[r][tx] = Wl[(long)(k0 + r) * N + n0 + tx];
    __syncthreads();
    long obase = (long)l * lsO + (long)(rowOff + n0) * K + k0;
    #pragma unroll
    for (int r = ty; r < 32; r += 8) {
        float v = t[tx][r];
        __nv_bfloat16 h = __float2bfloat16(v);
        float rem = v - __bfloat162float(h);
        hi[obase + (long)r * K + tx] = h;
        lo[obase + (long)r * K + tx] = __float2bfloat16(rem);
    }
}

// ---------------------------------------------------------------------------
// Activation hi/lo split
// ---------------------------------------------------------------------------
__global__ void split_kernel(const float* __restrict__ x,
                             __nv_bfloat16* __restrict__ hi,
                             __nv_bfloat16* __restrict__ lo, int n) {
    int i = blockIdx.x * 256 + threadIdx.x;
    if (i >= n) return;
    float v = x[i];
    __nv_bfloat16 h = __float2bfloat16(v);
    hi[i] = h;
    lo[i] = __float2bfloat16(v - __bfloat162float(h));
}

// QKV bias concat
__global__ void bcat_kernel(const float* __restrict__ bq, const float* __restrict__ bk,
                            const float* __restrict__ bv, float* __restrict__ o) {
    int i = blockIdx.x * 256 + threadIdx.x;
    if (i >= LLAYERS * 3 * DD) return;
    int l = i / (3 * DD), r = i % (3 * DD);
    float v = (r < DD) ? bq[l * DD + r]
            : (r < 2 * DD) ? bk[l * DD + r - DD]
            : bv[l * DD + r - 2 * DD];
    o[i] = v;
}

// ---------------------------------------------------------------------------
// bf16x3 tensor-core GEMM (mma.sync m16n8k16):
//   C = Ah@Bh^T + Ah@Bl^T + Al@Bh^T  [+bias][ReLU][+resid]
//   A [M,K] bf16 row-major, B [N,K] bf16 row-major, C fp32 [M,ldc].
//   CTA tile 128x128, BK=32, 8 warps (4x2) of 32x64, 2-stage cp.async.
//   Requires M%128==0, N%128==0, K%32==0.
// ---------------------------------------------------------------------------
#define SROWB 112                 // padded row bytes for 32 bf16 (64B data)
#define TILEB (128*SROWB)         // 14336 B per tile
#define STAGEB (4*TILEB)          // Ah,Al,Bh,Bl = 57344 B
#define HG_SMEM (2*STAGEB)        // 114688 B

__global__ __launch_bounds__(256, 1)
void hgemm_kernel(const __nv_bfloat16* __restrict__ Ah, const __nv_bfloat16* __restrict__ Al,
                  const __nv_bfloat16* __restrict__ Bh, const __nv_bfloat16* __restrict__ Bl,
                  float* __restrict__ C, const float* __restrict__ bias,
                  const float* __restrict__ resid, int relu, int K, int ldc) {
    extern __shared__ char sm[];
    const uint32_t sbase = s2u(sm);

    const int tid  = threadIdx.x;
    const int lane = tid & 31;
    const int wid  = tid >> 5;
    const int wm   = wid & 3;        // warp row  (4)
    const int wn   = wid >> 2;       // warp col  (2)

    const long m0 = (long)blockIdx.y * 128;
    const long n0 = (long)blockIdx.x * 128;

    const __nv_bfloat16* gAh = Ah + m0 * K;
    const __nv_bfloat16* gAl = Al + m0 * K;
    const __nv_bfloat16* gBh = Bh + n0 * K;
    const __nv_bfloat16* gBl = Bl + n0 * K;

    // load mapping: 512 16B-chunks per tile, 2 per thread
    const int c0row = tid >> 2, c0q = tid & 3;           // chunk tid
    const int c1row = (tid + 256) >> 2, c1q = tid & 3;   // chunk tid+256 (q same)

    float acc[2][8][4];
    #pragma unroll
    for (int i = 0; i < 2; i++)
        #pragma unroll
        for (int j = 0; j < 8; j++)
            #pragma unroll
            for (int r = 0; r < 4; r++) acc[i][j][r] = 0.0f;

    const int nk = K >> 5;

    // prologue: stage 0
    {
        uint32_t sb = sbase;
        uint32_t s0 = c0row * SROWB + c0q * 16;
        uint32_t s1 = c1row * SROWB + c1q * 16;
        long g0 = (long)c0row * K + c0q * 8;
        long g1 = (long)c1row * K + c1q * 8;
        cp16(sb + s0,             gAh + g0);  cp16(sb + s1,             gAh + g1);
        cp16(sb + TILEB + s0,     gAl + g0);  cp16(sb + TILEB + s1,     gAl + g1);
        cp16(sb + 2*TILEB + s0,   gBh + g0);  cp16(sb + 2*TILEB + s1,   gBh + g1);
        cp16(sb + 3*TILEB + s0,   gBl + g0);  cp16(sb + 3*TILEB + s1,   gBl + g1);
        asm volatile("cp.async.commit_group;");
    }

    for (int kc = 0; kc < nk; kc++) {
        if (kc + 1 < nk) {
            uint32_t sb = sbase + ((kc + 1) & 1) * STAGEB;
            int ke = (kc + 1) << 5;
            uint32_t s0 = c0row * SROWB + c0q * 16;
            uint32_t s1 = c1row * SROWB + c1q * 16;
            long g0 = (long)c0row * K + ke + c0q * 8;
            long g1 = (long)c1row * K + ke + c1q * 8;
            cp16(sb + s0,             gAh + g0);  cp16(sb + s1,             gAh + g1);
            cp16(sb + TILEB + s0,     gAl + g0);  cp16(sb + TILEB + s1,     gAl + g1);
            cp16(sb + 2*TILEB + s0,   gBh + g0);  cp16(sb + 2*TILEB + s1,   gBh + g1);
            cp16(sb + 3*TILEB + s0,   gBl + g0);  cp16(sb + 3*TILEB + s1,   gBl + g1);
            asm volatile("cp.async.commit_group;");
            asm volatile("cp.async.wait_group 1;");
        } else {
            asm volatile("cp.async.wait_group 0;");
        }
        __syncthreads();

        uint32_t sb = sbase + (kc & 1) * STAGEB;
        uint32_t sAh_ = sb, sAl_ = sb + TILEB, sBh_ = sb + 2*TILEB, sBl_ = sb + 3*TILEB;

        // ldmatrix lane addressing
        int lrow = lane & 15;
        int lcolB = ((lane >> 4) << 3) * 2;   // 0 or 16 bytes

        #pragma unroll
        for (int k16 = 0; k16 < 32; k16 += 16) {
            uint32_t koff = (uint32_t)(k16 * 2 + lcolB);
            uint32_t ah[2][4], al[2][4], bh[4][4], bl[4][4];
            #pragma unroll
            for (int mi = 0; mi < 2; mi++) {
                uint32_t ao = (uint32_t)((wm*32 + mi*16 + lrow) * SROWB) + koff;
                ldsm4(ah[mi], sAh_ + ao);
                ldsm4(al[mi], sAl_ + ao);
            }
            #pragma unroll
            for (int g = 0; g < 4; g++) {
                uint32_t bo = (uint32_t)((wn*64 + g*16 + lrow) * SROWB) + koff;
                ldsm4(bh[g], sBh_ + bo);
                ldsm4(bl[g], sBl_ + bo);
            }
            #pragma unroll
            for (int mi = 0; mi < 2; mi++) {
                #pragma unroll
                for (int nj = 0; nj < 8; nj++) {
                    int g = nj >> 1, sel = nj & 1;
                    mma16816(acc[mi][nj], ah[mi], bh[g][sel], bh[g][sel + 2]);
                    mma16816(acc[mi][nj], ah[mi], bl[g][sel], bl[g][sel + 2]);
                    mma16816(acc[mi][nj], al[mi], bh[g][sel], bh[g][sel + 2]);
                }
            }
        }
        __syncthreads();
    }

    // Epilogue
    const int rm = lane >> 2;
    const int rn = (lane & 3) * 2;
    #pragma unroll
    for (int mi = 0; mi < 2; mi++) {
        #pragma unroll
        for (int rr = 0; rr < 2; rr++) {
            long m = m0 + wm*32 + mi*16 + rr*8 + rm;
            float* crow = C + m * ldc + n0;
            const float* rrow = resid ? resid + m * ldc + n0 : nullptr;
            #pragma unroll
            for (int nj = 0; nj < 8; nj++) {
                int nl = wn*64 + nj*8 + rn;
                float v0 = acc[mi][nj][rr*2 + 0];
                float v1 = acc[mi][nj][rr*2 + 1];
                if (bias) { v0 += bias[n0 + nl]; v1 += bias[n0 + nl + 1]; }
                if (relu) { v0 = fmaxf(v0, 0.0f); v1 = fmaxf(v1, 0.0f); }
                if (rrow) { v0 += rrow[nl]; v1 += rrow[nl + 1]; }
                crow[nl]     = v0;
                crow[nl + 1] = v1;
            }
        }
    }
}

// ---------------------------------------------------------------------------
// Host-side helpers
// ---------------------------------------------------------------------------
static void launch_tgemm(const __nv_bfloat16* Ah, const __nv_bfloat16* Al,
                         const __nv_bfloat16* Bh, const __nv_bfloat16* Bl,
                         float* C, const float* bias, const float* resid,
                         int relu, int M, int N, int K, int ldc) {
    dim3 grid(N / 128, M / 128);
    hgemm_kernel<<<grid, 256, HG_SMEM>>>(Ah, Al, Bh, Bl, C, bias, resid, relu, K, ldc);
}

static void launch_fgemm(const float* A, const float* W, float* C,
                         int M, int N, int K, int lda, int ldw, int ldc,
                         float alpha, int transB, int causal,
                         int batch, int sub,
                         long sAo, long sAi, long sWo, long sWi, long sCo, long sCi) {
    dim3 grid((N + 127) / 128, (M + 127) / 128, batch);
    gemm_kernel<<<grid, 256>>>(A, W, C, M, N, K, lda, ldw, ldc,
                               alpha, transB, causal,
                               sAo, sAi, sWo, sWi, sCo, sCi, sub);
}

extern "C" void kernel_launch(void* const* d_in, const int* in_sizes, int n_in,
                              void* d_out, int out_size) {
    const int*   ids   = (const int*)  d_in[0];
    const float* tok   = (const float*)d_in[1];
    const float* pos   = (const float*)d_in[2];
    const float* Wq    = (const float*)d_in[3];
    const float* bq    = (const float*)d_in[4];
    const float* Wk    = (const float*)d_in[5];
    const float* bk    = (const float*)d_in[6];
    const float* Wv    = (const float*)d_in[7];
    const float* bv    = (const float*)d_in[8];
    const float* Wo    = (const float*)d_in[9];
    const float* bo    = (const float*)d_in[10];
    const float* W1    = (const float*)d_in[11];
    const float* b1    = (const float*)d_in[12];
    const float* W2    = (const float*)d_in[13];
    const float* b2    = (const float*)d_in[14];
    const float* ln1g  = (const float*)d_in[15];
    const float* ln1b  = (const float*)d_in[16];
    const float* ln2g  = (const float*)d_in[17];
    const float* ln2b  = (const float*)d_in[18];
    const float* lnfg  = (const float*)d_in[19];
    const float* lnfb  = (const float*)d_in[20];
    const float* Wout  = (const float*)d_in[21];
    const float* bout  = (const float*)d_in[22];
    float* out = (float*)d_out;

    cudaFuncSetAttribute(hgemm_kernel, cudaFuncAttributeMaxDynamicSharedMemorySize, HG_SMEM);

    float *px, *ph, *pqkv, *po, *pffn, *psc, *pbqkv;
    __nv_bfloat16 *pah, *pal;
    __nv_bfloat16 *wqkv_h, *wqkv_l, *wo_h, *wo_l, *w1_h, *w1_l, *w2_h, *w2_l, *wout_h, *wout_l;
    cudaGetSymbolAddress((void**)&px,    g_x);
    cudaGetSymbolAddress((void**)&ph,    g_h);
    cudaGetSymbolAddress((void**)&pqkv,  g_qkv);
    cudaGetSymbolAddress((void**)&po,    g_o);
    cudaGetSymbolAddress((void**)&pffn,  g_ffn);
    cudaGetSymbolAddress((void**)&psc,   g_sc);
    cudaGetSymbolAddress((void**)&pbqkv, g_bqkv);
    cudaGetSymbolAddress((void**)&pah,   g_ah);
    cudaGetSymbolAddress((void**)&pal,   g_al);
    cudaGetSymbolAddress((void**)&wqkv_h, g_wqkv_h);
    cudaGetSymbolAddress((void**)&wqkv_l, g_wqkv_l);
    cudaGetSymbolAddress((void**)&wo_h,   g_wo_h);
    cudaGetSymbolAddress((void**)&wo_l,   g_wo_l);
    cudaGetSymbolAddress((void**)&w1_h,   g_w1_h);
    cudaGetSymbolAddress((void**)&w1_l,   g_w1_l);
    cudaGetSymbolAddress((void**)&w2_h,   g_w2_h);
    cudaGetSymbolAddress((void**)&w2_l,   g_w2_l);
    cudaGetSymbolAddress((void**)&wout_h, g_wout_h);
    cudaGetSymbolAddress((void**)&wout_l, g_wout_l);

    // ---- Weight conversion (transpose + bf16 hi/lo split) ----
    {
        dim3 blk(32, 8);
        wtrans_kernel<<<dim3(DD/32, DD/32, LLAYERS), blk>>>(Wq, wqkv_h, wqkv_l, DD, DD,
            (long)DD*DD, (long)3*DD*DD, 0);
        wtrans_kernel<<<dim3(DD/32, DD/32, LLAYERS), blk>>>(Wk, wqkv_h, wqkv_l, DD, DD,
            (long)DD*DD, (long)3*DD*DD, DD);
        wtrans_kernel<<<dim3(DD/32, DD/32, LLAYERS), blk>>>(Wv, wqkv_h, wqkv_l, DD, DD,
            (long)DD*DD, (long)3*DD*DD, 2*DD);
        wtrans_kernel<<<dim3(DD/32, DD/32, LLAYERS), blk>>>(Wo, wo_h, wo_l, DD, DD,
            (long)DD*DD, (long)DD*DD, 0);
        wtrans_kernel<<<dim3(FF/32, DD/32, LLAYERS), blk>>>(W1, w1_h, w1_l, DD, FF,
            (long)DD*FF, (long)FF*DD, 0);
        wtrans_kernel<<<dim3(DD/32, FF/32, LLAYERS), blk>>>(W2, w2_h, w2_l, FF, DD,
            (long)FF*DD, (long)DD*FF, 0);
        wtrans_kernel<<<dim3(VV/32, DD/32, 1), blk>>>(Wout, wout_h, wout_l, DD, VV,
            0, 0, 0);
        bcat_kernel<<<(LLAYERS*3*DD + 255)/256, 256>>>(bq, bk, bv, pbqkv);
    }

    const float scale = 1.0f / 8.0f;  // 1/sqrt(64)

    // Embedding
    embed_kernel<<<(MM*(DD/4) + 255)/256, 256>>>(ids, tok, pos);

    for (int l = 0; l < LLAYERS; l++) {
        const float* bo_l = bo + (long)l * DD;
        const float* b1_l = b1 + (long)l * FF;
        const float* b2_l = b2 + (long)l * DD;

        // LN1 + split
        ln_kernel<<<MM, 256>>>(px, ph, ln1g + (long)l*DD, ln1b + (long)l*DD);
        split_kernel<<<(MM*DD + 255)/256, 256>>>(ph, pah, pal, MM*DD);

        // Fused QKV projection (tensor)
        launch_tgemm(pah, pal,
                     wqkv_h + (long)l*3*DD*DD, wqkv_l + (long)l*3*DD*DD,
                     pqkv, pbqkv + (long)l*3*DD, nullptr, 0,
                     MM, 3*DD, DD, 3*DD);

        // scores = scale * q @ k^T (fp32, causal tiles only)
        launch_fgemm(pqkv, pqkv + DD, psc,
                     SS, SS, DKK, 3*DD, 3*DD, SS,
                     scale, 1, 1,
                     BB*HH, HH,
                     (long)SS*3*DD, DKK,
                     (long)SS*3*DD, DKK,
                     (long)HH*SS*SS, (long)SS*SS);

        softmax_kernel<<<BB*HH*SS, 256>>>(psc);

        // o = attn @ v (fp32)
        launch_fgemm(psc, pqkv + 2*DD, po,
                     SS, DKK, SS, SS, 3*DD, DD,
                     1.0f, 0, 0,
                     BB*HH, HH,
                     (long)HH*SS*SS, (long)SS*SS,
                     (long)SS*3*DD, DKK,
                     (long)SS*DD, DKK);

        // O projection + residual (tensor)
        split_kernel<<<(MM*DD + 255)/256, 256>>>(po, pah, pal, MM*DD);
        launch_tgemm(pah, pal, wo_h + (long)l*DD*DD, wo_l + (long)l*DD*DD,
                     px, bo_l, px, 0, MM, DD, DD, DD);

        // LN2 + split
        ln_kernel<<<MM, 256>>>(px, ph, ln2g + (long)l*DD, ln2b + (long)l*DD);
        split_kernel<<<(MM*DD + 255)/256, 256>>>(ph, pah, pal, MM*DD);

        // FFN1 + ReLU (tensor)
        launch_tgemm(pah, pal, w1_h + (long)l*FF*DD, w1_l + (long)l*FF*DD,
                     pffn, b1_l, nullptr, 1, MM, FF, DD, FF);

        // FFN2 + residual (tensor)
        split_kernel<<<(MM*FF + 255)/256, 256>>>(pffn, pah, pal, MM*FF);
        launch_tgemm(pah, pal, w2_h + (long)l*DD*FF, w2_l + (long)l*DD*FF,
                     px, b2_l, px, 0, MM, DD, FF, DD);
    }

    // Final LN + logits (tensor)
    ln_kernel<<<MM, 256>>>(px, ph, lnfg, lnfb);
    split_kernel<<<(MM*DD + 255)/256, 256>>>(ph, pah, pal, MM*DD);
    launch_tgemm(pah, pal, wout_h, wout_l, out, bout, nullptr, 0,
                 MM, VV, DD, VV);
}

// round 6
// speedup vs baseline: 2.8803x; 1.1715x over previous
#include <cuda_runtime.h>
#include <cuda_bf16.h>
#include <math.h>
#include <stdint.h>

// Problem constants
#define BB 2
#define SS 1024
#define DD 1024
#define HH 16
#define DKK 64
#define FF 4096
#define VV 32000
#define LLAYERS 8
#define MM (BB*SS)          // 2048 token rows

// ---------------------------------------------------------------------------
// Scratch (allocation-free: __device__ globals)
// ---------------------------------------------------------------------------
__device__ float g_x[MM*DD];          // residual stream
__device__ float g_h[MM*DD];          // layernorm output
__device__ float g_o[MM*DD];          // attention output (pre-proj)
__device__ float g_ffn[MM*FF];        // FFN hidden
__device__ float g_sc[(long)BB*HH*SS*SS]; // attention scores [B,H,S,S] fp32
__device__ float g_bqkv[LLAYERS*3*DD];    // concat qkv bias

// Activation split buffers (bf16 hi/lo) — sized for largest (FFN hidden)
__device__ __nv_bfloat16 g_ah[MM*FF];
__device__ __nv_bfloat16 g_al[MM*FF];

// Attention bf16 split buffers
__device__ __nv_bfloat16 g_qh[MM*DD];
__device__ __nv_bfloat16 g_ql[MM*DD];
__device__ __nv_bfloat16 g_kh[MM*DD];
__device__ __nv_bfloat16 g_kl[MM*DD];
__device__ __nv_bfloat16 g_vth[(long)BB*DD*SS];  // v transposed [B][H*DK][S]
__device__ __nv_bfloat16 g_vtl[(long)BB*DD*SS];
__device__ __nv_bfloat16 g_ph[(long)BB*HH*SS*SS]; // probs hi
__device__ __nv_bfloat16 g_pl[(long)BB*HH*SS*SS]; // probs lo

// Weight transposed+split buffers [N,K] bf16
__device__ __nv_bfloat16 g_wqkv_h[(long)LLAYERS*3*DD*DD];
__device__ __nv_bfloat16 g_wqkv_l[(long)LLAYERS*3*DD*DD];
__device__ __nv_bfloat16 g_wo_h[(long)LLAYERS*DD*DD];
__device__ __nv_bfloat16 g_wo_l[(long)LLAYERS*DD*DD];
__device__ __nv_bfloat16 g_w1_h[(long)LLAYERS*DD*FF];
__device__ __nv_bfloat16 g_w1_l[(long)LLAYERS*DD*FF];
__device__ __nv_bfloat16 g_w2_h[(long)LLAYERS*FF*DD];
__device__ __nv_bfloat16 g_w2_l[(long)LLAYERS*FF*DD];
__device__ __nv_bfloat16 g_wout_h[(long)DD*VV];
__device__ __nv_bfloat16 g_wout_l[(long)DD*VV];

// ---------------------------------------------------------------------------
// Small PTX helpers (valid on plain sm_103 target)
// ---------------------------------------------------------------------------
__device__ __forceinline__ uint32_t s2u(const void* p) {
    return (uint32_t)__cvta_generic_to_shared(p);
}

__device__ __forceinline__ void cp16(uint32_t saddr, const void* g) {
    asm volatile("cp.async.cg.shared.global [%0], [%1], 16;" :: "r"(saddr), "l"(g));
}

// zero-fill variant: copies `bytes` (0 or 16), zero-fills remainder of 16
__device__ __forceinline__ void cp16z(uint32_t saddr, const void* g, int bytes) {
    asm volatile("cp.async.cg.shared.global [%0], [%1], 16, %2;"
                 :: "r"(saddr), "l"(g), "r"(bytes));
}

__device__ __forceinline__ void ldsm4(uint32_t* r, uint32_t addr) {
    asm volatile("ldmatrix.sync.aligned.m8n8.x4.shared.b16 {%0,%1,%2,%3}, [%4];"
                 : "=r"(r[0]), "=r"(r[1]), "=r"(r[2]), "=r"(r[3]) : "r"(addr));
}

__device__ __forceinline__ void mma16816(float* d, const uint32_t* a,
                                         uint32_t b0, uint32_t b1) {
    asm volatile(
        "mma.sync.aligned.m16n8k16.row.col.f32.bf16.bf16.f32 "
        "{%0,%1,%2,%3}, {%4,%5,%6,%7}, {%8,%9}, {%0,%1,%2,%3};"
        : "+f"(d[0]), "+f"(d[1]), "+f"(d[2]), "+f"(d[3])
        : "r"(a[0]), "r"(a[1]), "r"(a[2]), "r"(a[3]), "r"(b0), "r"(b1));
}

__device__ __forceinline__ void split2(float v, __nv_bfloat16& h, __nv_bfloat16& l) {
    h = __float2bfloat16(v);
    l = __float2bfloat16(v - __bfloat162float(h));
}

// ---------------------------------------------------------------------------
// Embedding
// ---------------------------------------------------------------------------
__global__ void embed_kernel(const int* __restrict__ ids,
                             const float* __restrict__ tok,
                             const float* __restrict__ pos) {
    int idx = blockIdx.x * blockDim.x + threadIdx.x;
    if (idx >= MM * (DD/4)) return;
    int m  = idx / (DD/4);
    int d4 = idx % (DD/4);
    int id = ids[m];
    int s  = m % SS;
    const float4* t4 = (const float4*)tok;
    const float4* p4 = (const float4*)pos;
    float4 a = t4[(long)id * (DD/4) + d4];
    float4 b = p4[(long)s  * (DD/4) + d4];
    a.x += b.x; a.y += b.y; a.z += b.z; a.w += b.w;
    ((float4*)g_x)[idx] = a;
}

// ---------------------------------------------------------------------------
// Block reductions (256 threads)
// ---------------------------------------------------------------------------
__device__ __forceinline__ float block_reduce_sum(float v) {
    __shared__ float sh[8];
    __shared__ float res;
    __syncthreads();
    #pragma unroll
    for (int o = 16; o > 0; o >>= 1) v += __shfl_xor_sync(0xffffffffu, v, o);
    int w = threadIdx.x >> 5, lane = threadIdx.x & 31;
    if (lane == 0) sh[w] = v;
    __syncthreads();
    if (w == 0) {
        v = (lane < 8) ? sh[lane] : 0.0f;
        #pragma unroll
        for (int o = 4; o > 0; o >>= 1) v += __shfl_xor_sync(0xffffffffu, v, o);
        if (lane == 0) res = v;
    }
    __syncthreads();
    return res;
}

__device__ __forceinline__ float block_reduce_max(float v) {
    __shared__ float sh[8];
    __shared__ float res;
    __syncthreads();
    #pragma unroll
    for (int o = 16; o > 0; o >>= 1) v = fmaxf(v, __shfl_xor_sync(0xffffffffu, v, o));
    int w = threadIdx.x >> 5, lane = threadIdx.x & 31;
    if (lane == 0) sh[w] = v;
    __syncthreads();
    if (w == 0) {
        v = (lane < 8) ? sh[lane] : -INFINITY;
        #pragma unroll
        for (int o = 4; o > 0; o >>= 1) v = fmaxf(v, __shfl_xor_sync(0xffffffffu, v, o));
        if (lane == 0) res = v;
    }
    __syncthreads();
    return res;
}

// ---------------------------------------------------------------------------
// LayerNorm
// ---------------------------------------------------------------------------
__global__ void ln_kernel(const float* __restrict__ x, float* __restrict__ y,
                          const float* __restrict__ g, const float* __restrict__ b) {
    int row = blockIdx.x;
    int t = threadIdx.x;
    const float4* xr = (const float4*)(x + (long)row * DD);
    float4 v = xr[t];
    float s = v.x + v.y + v.z + v.w;
    float mean = block_reduce_sum(s) * (1.0f / DD);
    float dx = v.x - mean, dy = v.y - mean, dz = v.z - mean, dw = v.w - mean;
    float sq = dx*dx + dy*dy + dz*dz + dw*dw;
    float var = block_reduce_sum(sq) * (1.0f / DD);
    float rs = rsqrtf(var + 1e-5f);
    const float4 gg = ((const float4*)g)[t];
    const float4 bb2 = ((const float4*)b)[t];
    float4 o;
    o.x = dx * rs * gg.x + bb2.x;
    o.y = dy * rs * gg.y + bb2.y;
    o.z = dz * rs * gg.z + bb2.z;
    o.w = dw * rs * gg.w + bb2.w;
    ((float4*)(y + (long)row * DD))[t] = o;
}

// ---------------------------------------------------------------------------
// Causal softmax: reads fp32 scores, writes bf16 hi/lo probs (0 for k>q)
// ---------------------------------------------------------------------------
__global__ void softmax_kernel(const float* __restrict__ sc,
                               __nv_bfloat16* __restrict__ ph,
                               __nv_bfloat16* __restrict__ pl) {
    long row = blockIdx.x;
    int q = (int)(row % SS);
    const float* p = sc + row * SS;
    __nv_bfloat16* oh = ph + row * SS;
    __nv_bfloat16* ol = pl + row * SS;
    int n = q + 1;
    int t = threadIdx.x;

    float mx = -INFINITY;
    for (int j = t; j < n; j += 256) mx = fmaxf(mx, p[j]);
    mx = block_reduce_max(mx);

    float sum = 0.0f;
    for (int j = t; j < n; j += 256) sum += __expf(p[j] - mx);
    sum = block_reduce_sum(sum);
    float inv = 1.0f / sum;

    const __nv_bfloat16 z = __float2bfloat16(0.0f);
    for (int j = t; j < SS; j += 256) {
        if (j < n) {
            float v = __expf(p[j] - mx) * inv;
            __nv_bfloat16 h, l;
            split2(v, h, l);
            oh[j] = h; ol[j] = l;
        } else {
            oh[j] = z; ol[j] = z;
        }
    }
}

// ---------------------------------------------------------------------------
// Weight transpose + bf16 hi/lo split:  W [K,N] fp32 -> out [N,K] bf16 x2
// ---------------------------------------------------------------------------
__global__ void wtrans_kernel(const float* __restrict__ W,
                              __nv_bfloat16* __restrict__ hi,
                              __nv_bfloat16* __restrict__ lo,
                              int K, int N, long lsW, long lsO, int rowOff) {
    __shared__ float t[32][33];
    int l = blockIdx.z;
    const float* Wl = W + (long)l * lsW;
    int n0 = blockIdx.x * 32, k0 = blockIdx.y * 32;
    int tx = threadIdx.x, ty = threadIdx.y;
    #pragma unroll
    for (int r = ty; r < 32; r += 8)
        t[r][tx] = Wl[(long)(k0 + r) * N + n0 + tx];
    __syncthreads();
    long obase = (long)l * lsO + (long)(rowOff + n0) * K + k0;
    #pragma unroll
    for (int r = ty; r < 32; r += 8) {
        float v = t[tx][r];
        __nv_bfloat16 h, lo2;
        split2(v, h, lo2);
        hi[obase + (long)r * K + tx] = h;
        lo[obase + (long)r * K + tx] = lo2;
    }
}

// ---------------------------------------------------------------------------
// Activation hi/lo split
// ---------------------------------------------------------------------------
__global__ void split_kernel(const float* __restrict__ x,
                             __nv_bfloat16* __restrict__ hi,
                             __nv_bfloat16* __restrict__ lo, int n) {
    int i = blockIdx.x * 256 + threadIdx.x;
    if (i >= n) return;
    __nv_bfloat16 h, l;
    split2(x[i], h, l);
    hi[i] = h;
    lo[i] = l;
}

// QKV bias concat
__global__ void bcat_kernel(const float* __restrict__ bq, const float* __restrict__ bk,
                            const float* __restrict__ bv, float* __restrict__ o) {
    int i = blockIdx.x * 256 + threadIdx.x;
    if (i >= LLAYERS * 3 * DD) return;
    int l = i / (3 * DD), r = i % (3 * DD);
    float v = (r < DD) ? bq[l * DD + r]
            : (r < 2 * DD) ? bk[l * DD + r - DD]
            : bv[l * DD + r - 2 * DD];
    o[i] = v;
}

// ---------------------------------------------------------------------------
// bf16x3 tensor-core GEMM (mma.sync m16n8k16):
//   C = Ah@Bh^T + Ah@Bl^T + Al@Bh^T
//   A [M,K-slice] bf16 (lda), B [N,K-slice] bf16 (ldb), C fp32 (ldc).
//   CTA tile 128x128, BK=32, 8 warps (4x2) of 32x64, 2-stage cp.async.
//   Batch z: zo=z/sub, zi=z%sub with per-operand stride pairs.
//   mode 0: write fp32 C [+bias][ReLU][+resid]
//   mode 1: QKV epilogue — +bias, then split-write q(*0.125),k bf16 hi/lo and
//           v transposed into g_vth/g_vtl.
//   causal: skip tiles with bx > by.
//   Requires M%128==0, K%32==0.
// ---------------------------------------------------------------------------
#define SROWB 112                 // padded row bytes for 32 bf16 (64B data)
#define TILEB (128*SROWB)         // 14336 B per tile
#define STAGEB (4*TILEB)          // Ah,Al,Bh,Bl = 57344 B
#define HG_SMEM (2*STAGEB)        // 114688 B

__global__ __launch_bounds__(256, 1)
void hgemm_kernel(const __nv_bfloat16* __restrict__ Ah, const __nv_bfloat16* __restrict__ Al,
                  const __nv_bfloat16* __restrict__ Bh, const __nv_bfloat16* __restrict__ Bl,
                  float* __restrict__ C, const float* __restrict__ bias,
                  const float* __restrict__ resid, int relu, int mode, int causal,
                  int M, int N, int K, int lda, int ldb, int ldc, int sub,
                  long sAo, long sAi, long sBo, long sBi, long sCo, long sCi) {
    if (causal && blockIdx.x > blockIdx.y) return;

    extern __shared__ char sm[];
    const uint32_t sbase = s2u(sm);

    const int tid  = threadIdx.x;
    const int lane = tid & 31;
    const int wid  = tid >> 5;
    const int wm   = wid & 3;        // warp row  (4)
    const int wn   = wid >> 2;       // warp col  (2)

    const int z = blockIdx.z;
    const int zo = z / sub, zi = z % sub;

    const long m0 = (long)blockIdx.y * 128;
    const long n0 = (long)blockIdx.x * 128;

    const __nv_bfloat16* gAh = Ah + zo * sAo + zi * sAi + m0 * lda;
    const __nv_bfloat16* gAl = Al + zo * sAo + zi * sAi + m0 * lda;
    const __nv_bfloat16* gBh = Bh + zo * sBo + zi * sBi + n0 * ldb;
    const __nv_bfloat16* gBl = Bl + zo * sBo + zi * sBi + n0 * ldb;

    // load mapping: 512 16B-chunks per tile, 2 per thread
    const int c0row = tid >> 2, cq = tid & 3;        // chunk tid  (rows 0..63)
    const int c1row = c0row + 64;                     // chunk tid+256 (rows 64..127)

    // B row validity (N may not be multiple of 128, e.g. attn@V N=64)
    const int nrem = N - (int)n0;
    const int b0ok = (c0row < nrem) ? 16 : 0;
    const int b1ok = (c1row < nrem) ? 16 : 0;
    const int b0r = (c0row < nrem) ? c0row : 0;
    const int b1r = (c1row < nrem) ? c1row : 0;

    float acc[2][8][4];
    #pragma unroll
    for (int i = 0; i < 2; i++)
        #pragma unroll
        for (int j = 0; j < 8; j++)
            #pragma unroll
            for (int r = 0; r < 4; r++) acc[i][j][r] = 0.0f;

    const int nk = K >> 5;

    {   // prologue: stage 0
        uint32_t sb = sbase;
        uint32_t s0 = c0row * SROWB + cq * 16;
        uint32_t s1 = c1row * SROWB + cq * 16;
        long a0 = (long)c0row * lda + cq * 8;
        long a1 = (long)c1row * lda + cq * 8;
        long g0 = (long)b0r * ldb + cq * 8;
        long g1 = (long)b1r * ldb + cq * 8;
        cp16(sb + s0,            gAh + a0);  cp16(sb + s1,            gAh + a1);
        cp16(sb + TILEB + s0,    gAl + a0);  cp16(sb + TILEB + s1,    gAl + a1);
        cp16z(sb + 2*TILEB + s0, gBh + g0, b0ok);  cp16z(sb + 2*TILEB + s1, gBh + g1, b1ok);
        cp16z(sb + 3*TILEB + s0, gBl + g0, b0ok);  cp16z(sb + 3*TILEB + s1, gBl + g1, b1ok);
        asm volatile("cp.async.commit_group;");
    }

    for (int kc = 0; kc < nk; kc++) {
        if (kc + 1 < nk) {
            uint32_t sb = sbase + ((kc + 1) & 1) * STAGEB;
            int ke = (kc + 1) << 5;
            uint32_t s0 = c0row * SROWB + cq * 16;
            uint32_t s1 = c1row * SROWB + cq * 16;
            long a0 = (long)c0row * lda + ke + cq * 8;
            long a1 = (long)c1row * lda + ke + cq * 8;
            long g0 = (long)b0r * ldb + ke + cq * 8;
            long g1 = (long)b1r * ldb + ke + cq * 8;
            cp16(sb + s0,            gAh + a0);  cp16(sb + s1,            gAh + a1);
            cp16(sb + TILEB + s0,    gAl + a0);  cp16(sb + TILEB + s1,    gAl + a1);
            cp16z(sb + 2*TILEB + s0, gBh + g0, b0ok);  cp16z(sb + 2*TILEB + s1, gBh + g1, b1ok);
            cp16z(sb + 3*TILEB + s0, gBl + g0, b0ok);  cp16z(sb + 3*TILEB + s1, gBl + g1, b1ok);
            asm volatile("cp.async.commit_group;");
            asm volatile("cp.async.wait_group 1;");
        } else {
            asm volatile("cp.async.wait_group 0;");
        }
        __syncthreads();

        uint32_t sb = sbase + (kc & 1) * STAGEB;
        uint32_t sAh_ = sb, sAl_ = sb + TILEB, sBh_ = sb + 2*TILEB, sBl_ = sb + 3*TILEB;

        int lrow = lane & 15;
        int lcolB = ((lane >> 4) << 3) * 2;   // 0 or 16 bytes

        #pragma unroll
        for (int k16 = 0; k16 < 32; k16 += 16) {
            uint32_t koff = (uint32_t)(k16 * 2 + lcolB);
            uint32_t ah[2][4], al[2][4], bh[4][4], bl[4][4];
            #pragma unroll
            for (int mi = 0; mi < 2; mi++) {
                uint32_t ao = (uint32_t)((wm*32 + mi*16 + lrow) * SROWB) + koff;
                ldsm4(ah[mi], sAh_ + ao);
                ldsm4(al[mi], sAl_ + ao);
            }
            #pragma unroll
            for (int g = 0; g < 4; g++) {
                uint32_t bo = (uint32_t)((wn*64 + g*16 + lrow) * SROWB) + koff;
                ldsm4(bh[g], sBh_ + bo);
                ldsm4(bl[g], sBl_ + bo);
            }
            #pragma unroll
            for (int mi = 0; mi < 2; mi++) {
                #pragma unroll
                for (int nj = 0; nj < 8; nj++) {
                    int g = nj >> 1, sel = nj & 1;
                    mma16816(acc[mi][nj], ah[mi], bh[g][sel], bh[g][sel + 2]);
                    mma16816(acc[mi][nj], ah[mi], bl[g][sel], bl[g][sel + 2]);
                    mma16816(acc[mi][nj], al[mi], bh[g][sel], bh[g][sel + 2]);
                }
            }
        }
        __syncthreads();
    }

    // Epilogue
    const int rm = lane >> 2;
    const int rn = (lane & 3) * 2;
    const long cz = zo * sCo + zi * sCi;

    #pragma unroll
    for (int mi = 0; mi < 2; mi++) {
        #pragma unroll
        for (int rr = 0; rr < 2; rr++) {
            long m = m0 + wm*32 + mi*16 + rr*8 + rm;
            #pragma unroll
            for (int nj = 0; nj < 8; nj++) {
                int nl = wn*64 + nj*8 + rn;
                if (nl >= nrem) continue;
                float v0 = acc[mi][nj][rr*2 + 0];
                float v1 = acc[mi][nj][rr*2 + 1];
                int gn = (int)n0 + nl;
                if (bias) { v0 += bias[gn]; v1 += bias[gn + 1]; }
                if (mode == 0) {
                    if (relu) { v0 = fmaxf(v0, 0.0f); v1 = fmaxf(v1, 0.0f); }
                    float* crow = C + cz + m * ldc;
                    if (resid) {
                        v0 += (resid + cz + m * ldc)[gn - 0];
                        v1 += (resid + cz + m * ldc)[gn + 1];
                    }
                    crow[gn]     = v0;
                    crow[gn + 1] = v1;
                } else {
                    // QKV epilogue: q (*0.125), k split; v transposed split
                    int b = (int)(m >> 10), s = (int)(m & 1023);
                    __nv_bfloat16 h0, l0, h1, l1;
                    if (gn < DD) {
                        split2(v0 * 0.125f, h0, l0);
                        split2(v1 * 0.125f, h1, l1);
                        long o = m * DD + gn;
                        g_qh[o] = h0; g_ql[o] = l0;
                        g_qh[o+1] = h1; g_ql[o+1] = l1;
                    } else if (gn < 2*DD) {
                        split2(v0, h0, l0);
                        split2(v1, h1, l1);
                        long o = m * DD + (gn - DD);
                        g_kh[o] = h0; g_kl[o] = l0;
                        g_kh[o+1] = h1; g_kl[o+1] = l1;
                    } else {
                        split2(v0, h0, l0);
                        split2(v1, h1, l1);
                        long o = (long)b * DD * SS + (long)(gn - 2*DD) * SS + s;
                        g_vth[o] = h0; g_vtl[o] = l0;
                        g_vth[o + SS] = h1; g_vtl[o + SS] = l1;
                    }
                }
            }
        }
    }
}

// ---------------------------------------------------------------------------
// Host-side helpers
// ---------------------------------------------------------------------------
static void launch_h(const __nv_bfloat16* Ah, const __nv_bfloat16* Al,
                     const __nv_bfloat16* Bh, const __nv_bfloat16* Bl,
                     float* C, const float* bias, const float* resid,
                     int relu, int mode, int causal,
                     int M, int N, int K, int lda, int ldb, int ldc,
                     int batch, int sub,
                     long sAo, long sAi, long sBo, long sBi, long sCo, long sCi) {
    dim3 grid((N + 127) / 128, M / 128, batch);
    hgemm_kernel<<<grid, 256, HG_SMEM>>>(Ah, Al, Bh, Bl, C, bias, resid,
                                         relu, mode, causal,
                                         M, N, K, lda, ldb, ldc, sub,
                                         sAo, sAi, sBo, sBi, sCo, sCi);
}

static void launch_dense(const __nv_bfloat16* Ah, const __nv_bfloat16* Al,
                         const __nv_bfloat16* Bh, const __nv_bfloat16* Bl,
                         float* C, const float* bias, const float* resid,
                         int relu, int mode, int M, int N, int K, int ldc) {
    launch_h(Ah, Al, Bh, Bl, C, bias, resid, relu, mode, 0,
             M, N, K, K, K, ldc, 1, 1, 0, 0, 0, 0, 0, 0);
}

extern "C" void kernel_launch(void* const* d_in, const int* in_sizes, int n_in,
                              void* d_out, int out_size) {
    const int*   ids   = (const int*)  d_in[0];
    const float* tok   = (const float*)d_in[1];
    const float* pos   = (const float*)d_in[2];
    const float* Wq    = (const float*)d_in[3];
    const float* bq    = (const float*)d_in[4];
    const float* Wk    = (const float*)d_in[5];
    const float* bk    = (const float*)d_in[6];
    const float* Wv    = (const float*)d_in[7];
    const float* bv    = (const float*)d_in[8];
    const float* Wo    = (const float*)d_in[9];
    const float* bo    = (const float*)d_in[10];
    const float* W1    = (const float*)d_in[11];
    const float* b1    = (const float*)d_in[12];
    const float* W2    = (const float*)d_in[13];
    const float* b2    = (const float*)d_in[14];
    const float* ln1g  = (const float*)d_in[15];
    const float* ln1b  = (const float*)d_in[16];
    const float* ln2g  = (const float*)d_in[17];
    const float* ln2b  = (const float*)d_in[18];
    const float* lnfg  = (const float*)d_in[19];
    const float* lnfb  = (const float*)d_in[20];
    const float* Wout  = (const float*)d_in[21];
    const float* bout  = (const float*)d_in[22];
    float* out = (float*)d_out;

    cudaFuncSetAttribute(hgemm_kernel, cudaFuncAttributeMaxDynamicSharedMemorySize, HG_SMEM);

    float *px, *ph, *po, *pffn, *psc, *pbqkv;
    __nv_bfloat16 *pah, *pal, *pqh, *pql, *pkh, *pkl, *pvth, *pvtl, *pph, *ppl;
    __nv_bfloat16 *wqkv_h, *wqkv_l, *wo_h, *wo_l, *w1_h, *w1_l, *w2_h, *w2_l, *wout_h, *wout_l;
    cudaGetSymbolAddress((void**)&px,    g_x);
    cudaGetSymbolAddress((void**)&ph,    g_h);
    cudaGetSymbolAddress((void**)&po,    g_o);
    cudaGetSymbolAddress((void**)&pffn,  g_ffn);
    cudaGetSymbolAddress((void**)&psc,   g_sc);
    cudaGetSymbolAddress((void**)&pbqkv, g_bqkv);
    cudaGetSymbolAddress((void**)&pah,   g_ah);
    cudaGetSymbolAddress((void**)&pal,   g_al);
    cudaGetSymbolAddress((void**)&pqh,   g_qh);
    cudaGetSymbolAddress((void**)&pql,   g_ql);
    cudaGetSymbolAddress((void**)&pkh,   g_kh);
    cudaGetSymbolAddress((void**)&pkl,   g_kl);
    cudaGetSymbolAddress((void**)&pvth,  g_vth);
    cudaGetSymbolAddress((void**)&pvtl,  g_vtl);
    cudaGetSymbolAddress((void**)&pph,   g_ph);
    cudaGetSymbolAddress((void**)&ppl,   g_pl);
    cudaGetSymbolAddress((void**)&wqkv_h, g_wqkv_h);
    cudaGetSymbolAddress((void**)&wqkv_l, g_wqkv_l);
    cudaGetSymbolAddress((void**)&wo_h,   g_wo_h);
    cudaGetSymbolAddress((void**)&wo_l,   g_wo_l);
    cudaGetSymbolAddress((void**)&w1_h,   g_w1_h);
    cudaGetSymbolAddress((void**)&w1_l,   g_w1_l);
    cudaGetSymbolAddress((void**)&w2_h,   g_w2_h);
    cudaGetSymbolAddress((void**)&w2_l,   g_w2_l);
    cudaGetSymbolAddress((void**)&wout_h, g_wout_h);
    cudaGetSymbolAddress((void**)&wout_l, g_wout_l);

    // ---- Weight conversion (transpose + bf16 hi/lo split) ----
    {
        dim3 blk(32, 8);
        wtrans_kernel<<<dim3(DD/32, DD/32, LLAYERS), blk>>>(Wq, wqkv_h, wqkv_l, DD, DD,
            (long)DD*DD, (long)3*DD*DD, 0);
        wtrans_kernel<<<dim3(DD/32, DD/32, LLAYERS), blk>>>(Wk, wqkv_h, wqkv_l, DD, DD,
            (long)DD*DD, (long)3*DD*DD, DD);
        wtrans_kernel<<<dim3(DD/32, DD/32, LLAYERS), blk>>>(Wv, wqkv_h, wqkv_l, DD, DD,
            (long)DD*DD, (long)3*DD*DD, 2*DD);
        wtrans_kernel<<<dim3(DD/32, DD/32, LLAYERS), blk>>>(Wo, wo_h, wo_l, DD, DD,
            (long)DD*DD, (long)DD*DD, 0);
        wtrans_kernel<<<dim3(FF/32, DD/32, LLAYERS), blk>>>(W1, w1_h, w1_l, DD, FF,
            (long)DD*FF, (long)FF*DD, 0);
        wtrans_kernel<<<dim3(DD/32, FF/32, LLAYERS), blk>>>(W2, w2_h, w2_l, FF, DD,
            (long)FF*DD, (long)DD*FF, 0);
        wtrans_kernel<<<dim3(VV/32, DD/32, 1), blk>>>(Wout, wout_h, wout_l, DD, VV,
            0, 0, 0);
        bcat_kernel<<<(LLAYERS*3*DD + 255)/256, 256>>>(bq, bk, bv, pbqkv);
    }

    // Embedding
    embed_kernel<<<(MM*(DD/4) + 255)/256, 256>>>(ids, tok, pos);

    for (int l = 0; l < LLAYERS; l++) {
        const float* bo_l = bo + (long)l * DD;
        const float* b1_l = b1 + (long)l * FF;
        const float* b2_l = b2 + (long)l * DD;

        // LN1 + split
        ln_kernel<<<MM, 256>>>(px, ph, ln1g + (long)l*DD, ln1b + (long)l*DD);
        split_kernel<<<(MM*DD + 255)/256, 256>>>(ph, pah, pal, MM*DD);

        // Fused QKV projection; epilogue emits q(scaled)/k/vT bf16 splits
        launch_dense(pah, pal,
                     wqkv_h + (long)l*3*DD*DD, wqkv_l + (long)l*3*DD*DD,
                     nullptr, pbqkv + (long)l*3*DD, nullptr, 0, 1,
                     MM, 3*DD, DD, 0);

        // scores = q_scaled @ k^T  (tensor, causal tiles only)
        launch_h(pqh, pql, pkh, pkl, psc, nullptr, nullptr, 0, 0, 1,
                 SS, SS, DKK, DD, DD, SS,
                 BB*HH, HH,
                 (long)SS*DD, DKK,            // A (q): b, h
                 (long)SS*DD, DKK,            // B (k): b, h
                 (long)HH*SS*SS, (long)SS*SS);// C (scores)

        // causal softmax -> bf16 hi/lo probs
        softmax_kernel<<<BB*HH*SS, 256>>>(psc, pph, ppl);

        // o = probs @ vT^T  (tensor, N=64 per head)
        launch_h(pph, ppl, pvth, pvtl, po, nullptr, nullptr, 0, 0, 0,
                 SS, DKK, SS, SS, SS, DD,
                 BB*HH, HH,
                 (long)HH*SS*SS, (long)SS*SS, // A (probs): b, h
                 (long)DD*SS, (long)DKK*SS,   // B (vT): b, h
                 (long)SS*DD, DKK);           // C (o): b, h-col
        // O projection + residual (in-place into x)
        split_kernel<<<(MM*DD + 255)/256, 256>>>(po, pah, pal, MM*DD);
        launch_dense(pah, pal, wo_h + (long)l*DD*DD, wo_l + (long)l*DD*DD,
                     px, bo_l, px, 0, 0, MM, DD, DD, DD);

        // LN2 + split
        ln_kernel<<<MM, 256>>>(px, ph, ln2g + (long)l*DD, ln2b + (long)l*DD);
        split_kernel<<<(MM*DD + 255)/256, 256>>>(ph, pah, pal, MM*DD);

        // FFN1 + ReLU
        launch_dense(pah, pal, w1_h + (long)l*FF*DD, w1_l + (long)l*FF*DD,
                     pffn, b1_l, nullptr, 1, 0, MM, FF, DD, FF);

        // FFN2 + residual
        split_kernel<<<(MM*FF + 255)/256, 256>>>(pffn, pah, pal, MM*FF);
        launch_dense(pah, pal, w2_h + (long)l*DD*FF, w2_l + (long)l*DD*FF,
                     px, b2_l, px, 0, 0, MM, DD, FF, DD);
    }

    // Final LN + logits
    ln_kernel<<<MM, 256>>>(px, ph, lnfg, lnfb);
    split_kernel<<<(MM*DD + 255)/256, 256>>>(ph, pah, pal, MM*DD);
    launch_dense(pah, pal, wout_h, wout_l, out, bout, nullptr, 0, 0,
                 MM, VV, DD, VV);
}